// round 12
// baseline (speedup 1.0000x reference)
#include <cuda_runtime.h>
#include <math.h>

// Problem constants
#define BB 2
#define TT 128
#define DD 1024
#define HH 8
#define RRm 8
#define DK 64
#define DV 64
#define NPROJ 2176           // 512 q | 512 k | 512 v | 64 beta | 64 tg | 512 g
#define NROWS 256            // B*T
#define CH 16                // scan chunk (timesteps staged in smem)

typedef unsigned long long u64;

// Scratch (no allocations allowed)
__device__ __align__(16) float g_proj[2 * NROWS * NPROJ];      // split-K partials (raw)
__device__ __align__(16) float g_projc[NROWS * NPROJ];         // combined + activated
__device__ __align__(16) float g_yr[RRm * NROWS * 512];        // per-r mode reads
__device__ __align__(16) float g_a[NROWS * 512];               // gated, r-reduced
__device__ __align__(16) float g_o[2 * NROWS * DD];            // out partials

// ---------------------------------------------------------------------------
// f32x2 helpers (ptxas never emits FFMA2 from C++; PTX only)
// ---------------------------------------------------------------------------
__device__ __forceinline__ u64 pack2(float lo, float hi) {
  u64 r; asm("mov.b64 %0, {%1, %2};" : "=l"(r) : "f"(lo), "f"(hi)); return r;
}
__device__ __forceinline__ void unpack2(u64 v, float& lo, float& hi) {
  asm("mov.b64 {%0, %1}, %2;" : "=f"(lo), "=f"(hi) : "l"(v));
}
__device__ __forceinline__ u64 fma2(u64 a, u64 b, u64 c) {
  u64 d; asm("fma.rn.f32x2 %0, %1, %2, %3;" : "=l"(d) : "l"(a), "l"(b), "l"(c)); return d;
}
__device__ __forceinline__ u64 mul2(u64 a, u64 b) {
  u64 d; asm("mul.rn.f32x2 %0, %1, %2;" : "=l"(d) : "l"(a), "l"(b)); return d;
}
__device__ __forceinline__ u64 neg2(u64 a) { return a ^ 0x8000000080000000ULL; }

union F4U { float4 f; u64 u[2]; };

__device__ __forceinline__ float sigmoidf_(float x) { return 1.f / (1.f + expf(-x)); }

// ---------------------------------------------------------------------------
// Fused projection GEMM, split-K=2: g_proj[z] = x[:, z*512:+512] @ W-half
// grid (34, 4, 2) = 272 CTAs, 256 threads, 4x4 microtile, double-buffered.
// ---------------------------------------------------------------------------
__global__ __launch_bounds__(256) void proj_gemm_kernel(
    const float* __restrict__ x,
    const float* __restrict__ Wq, const float* __restrict__ Wk,
    const float* __restrict__ Wv, const float* __restrict__ Wb,
    const float* __restrict__ Wtg, const float* __restrict__ Wg) {
  __shared__ float As[2][16][68];
  __shared__ float Bs[2][16][64];

  const int colBase = blockIdx.x * 64;
  const int rowBase = blockIdx.y * 64;
  const int kOff = blockIdx.z * 512;

  const float* W; int lc, ldw;
  if (colBase < 512)       { W = Wq;  lc = colBase;        ldw = 512; }
  else if (colBase < 1024) { W = Wk;  lc = colBase - 512;  ldw = 512; }
  else if (colBase < 1536) { W = Wv;  lc = colBase - 1024; ldw = 512; }
  else if (colBase < 1600) { W = Wb;  lc = colBase - 1536; ldw = 64;  }
  else if (colBase < 1664) { W = Wtg; lc = colBase - 1600; ldw = 64;  }
  else                     { W = Wg;  lc = colBase - 1664; ldw = 512; }

  const int tid = threadIdx.x;
  const int ty = tid >> 4, tx = tid & 15;
  const int lrA = tid >> 2, kgA = (tid & 3) * 4;
  const int lkB = tid >> 4, c4B = (tid & 15) << 2;

  u64 acc[4][2];
#pragma unroll
  for (int i = 0; i < 4; i++) { acc[i][0] = 0ULL; acc[i][1] = 0ULL; }

  const int NIT = 512 / 16;
  float4 av, bv;
  av = *(const float4*)(x + (rowBase + lrA) * DD + kOff + kgA);
  bv = *(const float4*)(W + (kOff + lkB) * ldw + lc + c4B);
  As[0][kgA + 0][lrA] = av.x; As[0][kgA + 1][lrA] = av.y;
  As[0][kgA + 2][lrA] = av.z; As[0][kgA + 3][lrA] = av.w;
  *(float4*)(&Bs[0][lkB][c4B]) = bv;
  __syncthreads();

  int cur = 0;
  for (int i = 0; i < NIT; i++) {
    if (i + 1 < NIT) {
      int kb = kOff + (i + 1) * 16;
      av = *(const float4*)(x + (rowBase + lrA) * DD + kb + kgA);
      bv = *(const float4*)(W + (kb + lkB) * ldw + lc + c4B);
    }
#pragma unroll
    for (int kk = 0; kk < 16; kk++) {
      float4 a = *(float4*)(&As[cur][kk][ty * 4]);
      F4U bb; bb.f = *(float4*)(&Bs[cur][kk][tx * 4]);
      u64 a0 = pack2(a.x, a.x);
      u64 a1 = pack2(a.y, a.y);
      u64 a2 = pack2(a.z, a.z);
      u64 a3 = pack2(a.w, a.w);
      acc[0][0] = fma2(a0, bb.u[0], acc[0][0]);
      acc[0][1] = fma2(a0, bb.u[1], acc[0][1]);
      acc[1][0] = fma2(a1, bb.u[0], acc[1][0]);
      acc[1][1] = fma2(a1, bb.u[1], acc[1][1]);
      acc[2][0] = fma2(a2, bb.u[0], acc[2][0]);
      acc[2][1] = fma2(a2, bb.u[1], acc[2][1]);
      acc[3][0] = fma2(a3, bb.u[0], acc[3][0]);
      acc[3][1] = fma2(a3, bb.u[1], acc[3][1]);
    }
    if (i + 1 < NIT) {
      int nxt = cur ^ 1;
      As[nxt][kgA + 0][lrA] = av.x; As[nxt][kgA + 1][lrA] = av.y;
      As[nxt][kgA + 2][lrA] = av.z; As[nxt][kgA + 3][lrA] = av.w;
      *(float4*)(&Bs[nxt][lkB][c4B]) = bv;
      __syncthreads();
      cur = nxt;
    }
  }

  float* outp = g_proj + blockIdx.z * (NROWS * NPROJ);
#pragma unroll
  for (int j = 0; j < 4; j++) {
    F4U o; o.u[0] = acc[j][0]; o.u[1] = acc[j][1];
    *(float4*)(outp + (rowBase + ty * 4 + j) * NPROJ + colBase + tx * 4) = o.f;
  }
}

// ---------------------------------------------------------------------------
// Combine split-K proj halves + apply sigmoid to activation cols (>=1536).
// ---------------------------------------------------------------------------
__global__ __launch_bounds__(256) void proj_combine_kernel() {
  int idx = blockIdx.x * blockDim.x + threadIdx.x;   // float4 index
  if (idx >= NROWS * NPROJ / 4) return;
  int e = idx * 4;
  int col = e % NPROJ;
  float4 a = *(const float4*)(g_proj + e);
  float4 b = *(const float4*)(g_proj + NROWS * NPROJ + e);
  float4 s; s.x = a.x + b.x; s.y = a.y + b.y; s.z = a.z + b.z; s.w = a.w + b.w;
  if (col >= 1536) {
    s.x = sigmoidf_(s.x); s.y = sigmoidf_(s.y);
    s.z = sigmoidf_(s.z); s.w = sigmoidf_(s.w);
  }
  *(float4*)(g_projc + e) = s;
}

// ---------------------------------------------------------------------------
// Sequential scan. One CTA per (b,h,r) chain: 128 CTAs, 512 threads
// (4 warps/SMSP to hide the per-step dependent-chain + shfl latency).
// Thread owns v = tid>>3 (row), k-slice [8*(tid%8), +8) as 4 f32x2 pairs.
// 8-lane shfl reductions (3 xor rounds); pred/rotq/kq overlap.
// CH=16 steps staged in smem, double-buffered, one sync per chunk.
// ---------------------------------------------------------------------------
__global__ __launch_bounds__(512) void scan_kernel(
    const float* __restrict__ mode_logits,
    const float* __restrict__ log_decay,
    const float* __restrict__ omega_log_scale) {
  __shared__ float sQ[2][CH][64];
  __shared__ float sK[2][CH][64];
  __shared__ float sV[2][CH][64];
  __shared__ float sB[2][CH];
  __shared__ float sT[2][CH];

  const int cid = blockIdx.x;        // 0..127
  const int b = cid >> 6;
  const int h = (cid >> 3) & 7;
  const int r = cid & 7;
  const int tid = threadIdx.x;
  const int v = tid >> 3;            // 0..63
  const int q8 = tid & 7;            // 0..7
  const int k0 = q8 * 8;             // 8 floats = 4 f32x2 pairs per thread

  // mode weight: softmax over R for this head
  float ml[RRm];
  float mx = -1e30f;
#pragma unroll
  for (int i = 0; i < RRm; i++) { ml[i] = mode_logits[h * RRm + i]; mx = fmaxf(mx, ml[i]); }
  float ssum = 0.f;
#pragma unroll
  for (int i = 0; i < RRm; i++) ssum += expf(ml[i] - mx);
  const float mw = expf(ml[r] - mx) / ssum;

  // rho = exp(-softplus(log_decay))
  const float ldv = log_decay[h * RRm + r];
  const float sp = (ldv > 20.f) ? ldv : log1pf(expf(ldv));
  const float rho = expf(-sp);
  const float osc = expf(omega_log_scale[h * RRm + r]);

  u64 cw2[4], sw2[4], sr2[4], si2[4];
  const float c_ln = 9.210340371976184f / 64.f;  // ln(10000)/64
#pragma unroll
  for (int p = 0; p < 4; p++) {
    float pv = (float)(k0 + 2 * p);              // even -> (k & ~1) identical for pair
    float om = osc * expf(-pv * c_ln);
    float c = cosf(om), s = sinf(om);
    cw2[p] = pack2(c, c);
    sw2[p] = pack2(s, s);
    sr2[p] = 0ULL;
    si2[p] = 0ULL;
  }

  // Cooperative chunk loading: 512 threads -> (step ls = tid>>5, part sub = tid&31)
  // sub 0..15 load q[sub] and v[sub]; sub 16..31 load k[sub-16]; sub 16/17 also b/t.
  const int ls = tid >> 5;       // 0..15
  const int sub = tid & 31;      // 0..31
  const bool isQ = (sub < 16);
  const int lp = isQ ? sub : (sub - 16);
  const float* gpb = g_projc + (b * TT) * NPROJ;
  float* ybase = g_yr + r * (NROWS * 512) + (b * TT) * 512 + h * DV + v;

  float4 qkf, vf;
  float bf = 0.f, tf = 0.f;
  {
    const float* row = gpb + ls * NPROJ + h * 64;
    if (isQ) {
      qkf = *(const float4*)(row + lp * 4);            // q part
      vf  = *(const float4*)(row + 1024 + lp * 4);     // v part
    } else {
      qkf = *(const float4*)(row + 512 + lp * 4);      // k part
    }
    if (sub == 16) bf = gpb[ls * NPROJ + 1536 + h * RRm + r];
    if (sub == 17) tf = gpb[ls * NPROJ + 1600 + h * RRm + r];
  }
  if (isQ) {
    *(float4*)(&sQ[0][ls][lp * 4]) = qkf;
    *(float4*)(&sV[0][ls][lp * 4]) = vf;
  } else {
    *(float4*)(&sK[0][ls][lp * 4]) = qkf;
  }
  if (sub == 16) sB[0][ls] = bf;
  if (sub == 17) sT[0][ls] = tf;
  __syncthreads();

  const int NCH = TT / CH;
  int cur = 0;
  for (int c = 0; c < NCH; c++) {
    // Prefetch next chunk into registers (overlaps with the 16-step compute)
    if (c + 1 < NCH) {
      const float* row = gpb + ((c + 1) * CH + ls) * NPROJ + h * 64;
      if (isQ) {
        qkf = *(const float4*)(row + lp * 4);
        vf  = *(const float4*)(row + 1024 + lp * 4);
      } else {
        qkf = *(const float4*)(row + 512 + lp * 4);
      }
      if (sub == 16) bf = gpb[((c + 1) * CH + ls) * NPROJ + 1536 + h * RRm + r];
      if (sub == 17) tf = gpb[((c + 1) * CH + ls) * NPROJ + 1600 + h * RRm + r];
    }

    for (int tt = 0; tt < CH; tt++) {
      u64 kt2[4], qt2[4];
      {
        F4U kv0; kv0.f = *(const float4*)(&sK[cur][tt][k0]);
        F4U kv1; kv1.f = *(const float4*)(&sK[cur][tt][k0 + 4]);
        F4U qv0; qv0.f = *(const float4*)(&sQ[cur][tt][k0]);
        F4U qv1; qv1.f = *(const float4*)(&sQ[cur][tt][k0 + 4]);
        kt2[0] = kv0.u[0]; kt2[1] = kv0.u[1]; kt2[2] = kv1.u[0]; kt2[3] = kv1.u[1];
        qt2[0] = qv0.u[0]; qt2[1] = qv0.u[1]; qt2[2] = qv1.u[0]; qt2[3] = qv1.u[1];
      }
      const float vtv  = sV[cur][tt][v];
      const float beta = sB[cur][tt];
      const float tg   = sT[cur][tt];
      const float decay = tg * rho;
      const u64 decay2 = pack2(decay, decay);

      // rotation + three accumulators (pred critical; rotq/kq off-path)
      u64 pred2 = 0ULL, rotq2 = 0ULL, kq2 = 0ULL;
#pragma unroll
      for (int p = 0; p < 4; p++) {
        u64 dc = mul2(decay2, cw2[p]);
        u64 ds = mul2(decay2, sw2[p]);
        u64 m1 = mul2(ds, si2[p]);
        u64 rr = fma2(dc, sr2[p], neg2(m1));
        u64 m2 = mul2(dc, si2[p]);
        si2[p] = fma2(ds, sr2[p], m2);
        sr2[p] = rr;                       // sr temporarily holds rot_r
        pred2 = fma2(rr, kt2[p], pred2);
        rotq2 = fma2(rr, qt2[p], rotq2);
        kq2   = fma2(kt2[p], qt2[p], kq2);
      }
      float plo, phi, rqlo, rqhi, kqlo, kqhi;
      unpack2(pred2, plo, phi);
      unpack2(rotq2, rqlo, rqhi);
      unpack2(kq2, kqlo, kqhi);
      float pred = plo + phi;
      float rotq = rqlo + rqhi;
      float kq = kqlo + kqhi;
      // three independent 8-lane shfl reductions; latencies overlap
      pred += __shfl_xor_sync(0xffffffffu, pred, 1);
      rotq += __shfl_xor_sync(0xffffffffu, rotq, 1);
      kq   += __shfl_xor_sync(0xffffffffu, kq, 1);
      pred += __shfl_xor_sync(0xffffffffu, pred, 2);
      rotq += __shfl_xor_sync(0xffffffffu, rotq, 2);
      kq   += __shfl_xor_sync(0xffffffffu, kq, 2);
      pred += __shfl_xor_sync(0xffffffffu, pred, 4);
      rotq += __shfl_xor_sync(0xffffffffu, rotq, 4);
      kq   += __shfl_xor_sync(0xffffffffu, kq, 4);

      const float w = beta * (vtv - pred);
      const u64 w2 = pack2(w, w);

      // state update (inter-step path); rd needs no second reduction
#pragma unroll
      for (int p = 0; p < 4; p++)
        sr2[p] = fma2(w2, kt2[p], sr2[p]); // sr_new = rot_r + beta*err*k

      if (q8 == 0) ybase[(c * CH + tt) * 512] = mw * fmaf(w, kq, rotq);
    }

    if (c + 1 < NCH) {
      int nxt = cur ^ 1;
      if (isQ) {
        *(float4*)(&sQ[nxt][ls][lp * 4]) = qkf;
        *(float4*)(&sV[nxt][ls][lp * 4]) = vf;
      } else {
        *(float4*)(&sK[nxt][ls][lp * 4]) = qkf;
      }
      if (sub == 16) sB[nxt][ls] = bf;
      if (sub == 17) sT[nxt][ls] = tf;
      __syncthreads();
      cur = nxt;
    }
  }
}

// ---------------------------------------------------------------------------
// Reduce over r + apply gate: g_a[row][c] = gate[row][c] * sum_r g_yr
// (gate already sigmoided in g_projc)
// ---------------------------------------------------------------------------
__global__ __launch_bounds__(256) void reduce_y_kernel() {
  int idx = blockIdx.x * blockDim.x + threadIdx.x;   // float4 index
  if (idx >= NROWS * 512 / 4) return;
  int row = idx >> 7;           // 128 float4 per row
  int c4 = (idx & 127) << 2;
  float4 s = *(const float4*)(g_yr + row * 512 + c4);
#pragma unroll
  for (int r = 1; r < RRm; r++) {
    float4 t = *(const float4*)(g_yr + r * (NROWS * 512) + row * 512 + c4);
    s.x += t.x; s.y += t.y; s.z += t.z; s.w += t.w;
  }
  float4 g = *(const float4*)(g_projc + row * NPROJ + 1664 + c4);
  s.x *= g.x; s.y *= g.y; s.z *= g.z; s.w *= g.w;
  *(float4*)(g_a + row * 512 + c4) = s;
}

// ---------------------------------------------------------------------------
// Output GEMM, split-K=2: g_o[z] = g_a[:, z*256:+256] @ Wo-half
// grid (16, 4, 2) = 128 CTAs, 256 threads, 4x4 microtile, double-buffered.
// ---------------------------------------------------------------------------
__global__ __launch_bounds__(256) void out_gemm_kernel(
    const float* __restrict__ Wo) {
  __shared__ float As[2][16][68];
  __shared__ float Bs[2][16][64];

  const int colBase = blockIdx.x * 64;  // 0..1023
  const int rowBase = blockIdx.y * 64;  // 0..255
  const int kOff = blockIdx.z * 256;

  const int tid = threadIdx.x;
  const int ty = tid >> 4, tx = tid & 15;
  const int lrA = tid >> 2, kgA = (tid & 3) * 4;
  const int lkB = tid >> 4, c4B = (tid & 15) << 2;

  u64 acc[4][2];
#pragma unroll
  for (int i = 0; i < 4; i++) { acc[i][0] = 0ULL; acc[i][1] = 0ULL; }

  const int NIT = 256 / 16;
  float4 av, bv;
  av = *(const float4*)(g_a + (rowBase + lrA) * 512 + kOff + kgA);
  bv = *(const float4*)(Wo + (kOff + lkB) * DD + colBase + c4B);
  As[0][kgA + 0][lrA] = av.x; As[0][kgA + 1][lrA] = av.y;
  As[0][kgA + 2][lrA] = av.z; As[0][kgA + 3][lrA] = av.w;
  *(float4*)(&Bs[0][lkB][c4B]) = bv;
  __syncthreads();

  int cur = 0;
  for (int i = 0; i < NIT; i++) {
    if (i + 1 < NIT) {
      int kb = kOff + (i + 1) * 16;
      av = *(const float4*)(g_a + (rowBase + lrA) * 512 + kb + kgA);
      bv = *(const float4*)(Wo + (kb + lkB) * DD + colBase + c4B);
    }
#pragma unroll
    for (int kk = 0; kk < 16; kk++) {
      float4 a = *(float4*)(&As[cur][kk][ty * 4]);
      F4U bb; bb.f = *(float4*)(&Bs[cur][kk][tx * 4]);
      u64 a0 = pack2(a.x, a.x);
      u64 a1 = pack2(a.y, a.y);
      u64 a2 = pack2(a.z, a.z);
      u64 a3 = pack2(a.w, a.w);
      acc[0][0] = fma2(a0, bb.u[0], acc[0][0]);
      acc[0][1] = fma2(a0, bb.u[1], acc[0][1]);
      acc[1][0] = fma2(a1, bb.u[0], acc[1][0]);
      acc[1][1] = fma2(a1, bb.u[1], acc[1][1]);
      acc[2][0] = fma2(a2, bb.u[0], acc[2][0]);
      acc[2][1] = fma2(a2, bb.u[1], acc[2][1]);
      acc[3][0] = fma2(a3, bb.u[0], acc[3][0]);
      acc[3][1] = fma2(a3, bb.u[1], acc[3][1]);
    }
    if (i + 1 < NIT) {
      int nxt = cur ^ 1;
      As[nxt][kgA + 0][lrA] = av.x; As[nxt][kgA + 1][lrA] = av.y;
      As[nxt][kgA + 2][lrA] = av.z; As[nxt][kgA + 3][lrA] = av.w;
      *(float4*)(&Bs[nxt][lkB][c4B]) = bv;
      __syncthreads();
      cur = nxt;
    }
  }

  float* outp = g_o + blockIdx.z * (NROWS * DD);
#pragma unroll
  for (int j = 0; j < 4; j++) {
    F4U o; o.u[0] = acc[j][0]; o.u[1] = acc[j][1];
    *(float4*)(outp + (rowBase + ty * 4 + j) * DD + colBase + tx * 4) = o.f;
  }
}

// ---------------------------------------------------------------------------
// Sum the two out partials into d_out.
// ---------------------------------------------------------------------------
__global__ __launch_bounds__(256) void out_sum_kernel(float* __restrict__ out) {
  int idx = blockIdx.x * blockDim.x + threadIdx.x;   // float4 index
  if (idx >= NROWS * DD / 4) return;
  float4 a = *(const float4*)(g_o + idx * 4);
  float4 b = *(const float4*)(g_o + NROWS * DD + idx * 4);
  float4 s; s.x = a.x + b.x; s.y = a.y + b.y; s.z = a.z + b.z; s.w = a.w + b.w;
  *(float4*)(out + idx * 4) = s;
}

// ---------------------------------------------------------------------------
// Entry point
// ---------------------------------------------------------------------------
extern "C" void kernel_launch(void* const* d_in, const int* in_sizes, int n_in,
                              void* d_out, int out_size) {
  const float* x    = (const float*)d_in[0];
  const float* Wq   = (const float*)d_in[1];
  const float* Wk   = (const float*)d_in[2];
  const float* Wv   = (const float*)d_in[3];
  const float* Wb   = (const float*)d_in[4];
  const float* Wtg  = (const float*)d_in[5];
  const float* ml   = (const float*)d_in[6];
  const float* ldc  = (const float*)d_in[7];
  const float* oms  = (const float*)d_in[8];
  const float* Wg   = (const float*)d_in[9];
  const float* Wo   = (const float*)d_in[10];
  float* out = (float*)d_out;

  proj_gemm_kernel<<<dim3(NPROJ / 64, NROWS / 64, 2), 256>>>(x, Wq, Wk, Wv, Wb, Wtg, Wg);
  proj_combine_kernel<<<(NROWS * NPROJ / 4 + 255) / 256, 256>>>();
  scan_kernel<<<BB * HH * RRm, 512>>>(ml, ldc, oms);
  reduce_y_kernel<<<(NROWS * 512 / 4 + 255) / 256, 256>>>();
  out_gemm_kernel<<<dim3(DD / 64, NROWS / 64, 2), 256>>>(Wo);
  out_sum_kernel<<<(NROWS * DD / 4 + 255) / 256, 256>>>(out);
}

// round 13
// speedup vs baseline: 1.0919x; 1.0919x over previous
#include <cuda_runtime.h>
#include <math.h>

// Problem constants
#define BB 2
#define TT 128
#define DD 1024
#define HH 8
#define RRm 8
#define DK 64
#define DV 64
#define NPROJ 2176           // 512 q | 512 k | 512 v | 64 beta | 64 tg | 512 g
#define NROWS 256            // B*T
#define CH 16                // scan chunk (timesteps staged in smem)

typedef unsigned long long u64;

// Scratch (no allocations allowed)
__device__ __align__(16) float g_proj[2 * NROWS * NPROJ];      // split-K partials (raw)
__device__ __align__(16) float g_projc[NROWS * NPROJ];         // combined + activated
__device__ __align__(16) float g_yr[RRm * NROWS * 512];        // per-r mode reads
__device__ __align__(16) float g_a[NROWS * 512];               // gated, r-reduced
__device__ __align__(16) float g_o[4 * NROWS * DD];            // out partials (split-K=4)

// ---------------------------------------------------------------------------
// f32x2 helpers (ptxas never emits FFMA2 from C++; PTX only)
// ---------------------------------------------------------------------------
__device__ __forceinline__ u64 pack2(float lo, float hi) {
  u64 r; asm("mov.b64 %0, {%1, %2};" : "=l"(r) : "f"(lo), "f"(hi)); return r;
}
__device__ __forceinline__ void unpack2(u64 v, float& lo, float& hi) {
  asm("mov.b64 {%0, %1}, %2;" : "=f"(lo), "=f"(hi) : "l"(v));
}
__device__ __forceinline__ u64 fma2(u64 a, u64 b, u64 c) {
  u64 d; asm("fma.rn.f32x2 %0, %1, %2, %3;" : "=l"(d) : "l"(a), "l"(b), "l"(c)); return d;
}
__device__ __forceinline__ u64 mul2(u64 a, u64 b) {
  u64 d; asm("mul.rn.f32x2 %0, %1, %2;" : "=l"(d) : "l"(a), "l"(b)); return d;
}
__device__ __forceinline__ u64 neg2(u64 a) { return a ^ 0x8000000080000000ULL; }

union F4U { float4 f; u64 u[2]; };

__device__ __forceinline__ float sigmoidf_(float x) { return 1.f / (1.f + expf(-x)); }

// ---------------------------------------------------------------------------
// Fused projection GEMM, split-K=2: g_proj[z] = x[:, z*512:+512] @ W-half
// grid (34, 4, 2) = 272 CTAs, 256 threads, 4x4 microtile, double-buffered.
// ---------------------------------------------------------------------------
__global__ __launch_bounds__(256) void proj_gemm_kernel(
    const float* __restrict__ x,
    const float* __restrict__ Wq, const float* __restrict__ Wk,
    const float* __restrict__ Wv, const float* __restrict__ Wb,
    const float* __restrict__ Wtg, const float* __restrict__ Wg) {
  __shared__ float As[2][16][68];
  __shared__ float Bs[2][16][64];

  const int colBase = blockIdx.x * 64;
  const int rowBase = blockIdx.y * 64;
  const int kOff = blockIdx.z * 512;

  const float* W; int lc, ldw;
  if (colBase < 512)       { W = Wq;  lc = colBase;        ldw = 512; }
  else if (colBase < 1024) { W = Wk;  lc = colBase - 512;  ldw = 512; }
  else if (colBase < 1536) { W = Wv;  lc = colBase - 1024; ldw = 512; }
  else if (colBase < 1600) { W = Wb;  lc = colBase - 1536; ldw = 64;  }
  else if (colBase < 1664) { W = Wtg; lc = colBase - 1600; ldw = 64;  }
  else                     { W = Wg;  lc = colBase - 1664; ldw = 512; }

  const int tid = threadIdx.x;
  const int ty = tid >> 4, tx = tid & 15;
  const int lrA = tid >> 2, kgA = (tid & 3) * 4;
  const int lkB = tid >> 4, c4B = (tid & 15) << 2;

  u64 acc[4][2];
#pragma unroll
  for (int i = 0; i < 4; i++) { acc[i][0] = 0ULL; acc[i][1] = 0ULL; }

  const int NIT = 512 / 16;
  float4 av, bv;
  av = *(const float4*)(x + (rowBase + lrA) * DD + kOff + kgA);
  bv = *(const float4*)(W + (kOff + lkB) * ldw + lc + c4B);
  As[0][kgA + 0][lrA] = av.x; As[0][kgA + 1][lrA] = av.y;
  As[0][kgA + 2][lrA] = av.z; As[0][kgA + 3][lrA] = av.w;
  *(float4*)(&Bs[0][lkB][c4B]) = bv;
  __syncthreads();

  int cur = 0;
  for (int i = 0; i < NIT; i++) {
    if (i + 1 < NIT) {
      int kb = kOff + (i + 1) * 16;
      av = *(const float4*)(x + (rowBase + lrA) * DD + kb + kgA);
      bv = *(const float4*)(W + (kb + lkB) * ldw + lc + c4B);
    }
#pragma unroll
    for (int kk = 0; kk < 16; kk++) {
      float4 a = *(float4*)(&As[cur][kk][ty * 4]);
      F4U bb; bb.f = *(float4*)(&Bs[cur][kk][tx * 4]);
      u64 a0 = pack2(a.x, a.x);
      u64 a1 = pack2(a.y, a.y);
      u64 a2 = pack2(a.z, a.z);
      u64 a3 = pack2(a.w, a.w);
      acc[0][0] = fma2(a0, bb.u[0], acc[0][0]);
      acc[0][1] = fma2(a0, bb.u[1], acc[0][1]);
      acc[1][0] = fma2(a1, bb.u[0], acc[1][0]);
      acc[1][1] = fma2(a1, bb.u[1], acc[1][1]);
      acc[2][0] = fma2(a2, bb.u[0], acc[2][0]);
      acc[2][1] = fma2(a2, bb.u[1], acc[2][1]);
      acc[3][0] = fma2(a3, bb.u[0], acc[3][0]);
      acc[3][1] = fma2(a3, bb.u[1], acc[3][1]);
    }
    if (i + 1 < NIT) {
      int nxt = cur ^ 1;
      As[nxt][kgA + 0][lrA] = av.x; As[nxt][kgA + 1][lrA] = av.y;
      As[nxt][kgA + 2][lrA] = av.z; As[nxt][kgA + 3][lrA] = av.w;
      *(float4*)(&Bs[nxt][lkB][c4B]) = bv;
      __syncthreads();
      cur = nxt;
    }
  }

  float* outp = g_proj + blockIdx.z * (NROWS * NPROJ);
#pragma unroll
  for (int j = 0; j < 4; j++) {
    F4U o; o.u[0] = acc[j][0]; o.u[1] = acc[j][1];
    *(float4*)(outp + (rowBase + ty * 4 + j) * NPROJ + colBase + tx * 4) = o.f;
  }
}

// ---------------------------------------------------------------------------
// Combine split-K proj halves + apply sigmoid to activation cols (>=1536).
// ---------------------------------------------------------------------------
__global__ __launch_bounds__(256) void proj_combine_kernel() {
  int idx = blockIdx.x * blockDim.x + threadIdx.x;   // float4 index
  if (idx >= NROWS * NPROJ / 4) return;
  int e = idx * 4;
  int col = e % NPROJ;
  float4 a = *(const float4*)(g_proj + e);
  float4 b = *(const float4*)(g_proj + NROWS * NPROJ + e);
  float4 s; s.x = a.x + b.x; s.y = a.y + b.y; s.z = a.z + b.z; s.w = a.w + b.w;
  if (col >= 1536) {
    s.x = sigmoidf_(s.x); s.y = sigmoidf_(s.y);
    s.z = sigmoidf_(s.z); s.w = sigmoidf_(s.w);
  }
  *(float4*)(g_projc + e) = s;
}

// ---------------------------------------------------------------------------
// Sequential scan. One CTA per (b,h,r) chain: 128 CTAs, 256 threads
// (R10 layout: thread = v row (tid>>2) x k-quarter (tid&3), 8 f32x2 pairs).
// Pipelined recurrence: with sr_t = r_{t-1} + w_{t-1} k_{t-1},
//   pred_t = <a,k_t> + w_{t-1}<b,k_t>,  a = dc*r - ds*i,  b = dc*k_prev
//   r_t = a + w_{t-1} b,  i_t = c + w_{t-1} d  (c = ds*r + dc*i, d = ds*k_prev)
// -> the Ak/Bk dots AND their shfl reductions are independent of w_{t-1};
// the loop-carried chain shrinks to ~2 fma + the state materialization.
// y_t = mw*(<r_t,q_t> + w_t<k_t,q_t>); its reduction is off the w-chain.
// ---------------------------------------------------------------------------
__global__ __launch_bounds__(256) void scan_kernel(
    const float* __restrict__ mode_logits,
    const float* __restrict__ log_decay,
    const float* __restrict__ omega_log_scale) {
  __shared__ float sQ[2][CH][64];
  __shared__ float sK[2][CH][64];
  __shared__ float sV[2][CH][64];
  __shared__ float sB[2][CH];
  __shared__ float sT[2][CH];

  const int cid = blockIdx.x;        // 0..127
  const int b = cid >> 6;
  const int h = (cid >> 3) & 7;
  const int r = cid & 7;
  const int tid = threadIdx.x;
  const int v = tid >> 2;
  const int q4 = tid & 3;
  const int k0 = q4 * 16;

  // mode weight: softmax over R for this head
  float ml[RRm];
  float mx = -1e30f;
#pragma unroll
  for (int i = 0; i < RRm; i++) { ml[i] = mode_logits[h * RRm + i]; mx = fmaxf(mx, ml[i]); }
  float ssum = 0.f;
#pragma unroll
  for (int i = 0; i < RRm; i++) ssum += expf(ml[i] - mx);
  const float mw = expf(ml[r] - mx) / ssum;

  // rho = exp(-softplus(log_decay))
  const float ldv = log_decay[h * RRm + r];
  const float sp = (ldv > 20.f) ? ldv : log1pf(expf(ldv));
  const float rho = expf(-sp);
  const float osc = expf(omega_log_scale[h * RRm + r]);

  u64 cw2[8], sw2[8], r2[8], i2[8], kp2[8];
  const float c_ln = 9.210340371976184f / 64.f;  // ln(10000)/64
#pragma unroll
  for (int p = 0; p < 8; p++) {
    float pv = (float)(k0 + 2 * p);              // even -> (k & ~1) identical for pair
    float om = osc * expf(-pv * c_ln);
    float c = cosf(om), s = sinf(om);
    cw2[p] = pack2(c, c);
    sw2[p] = pack2(s, s);
    r2[p] = 0ULL;
    i2[p] = 0ULL;
    kp2[p] = 0ULL;
  }
  float w_prev = 0.f;

  // Cooperative chunk loading: thread -> (step ls, float4 part lp)
  const int ls = tid >> 4;       // 0..15
  const int lp = tid & 15;       // 0..15
  const float* gpb = g_projc + (b * TT) * NPROJ;
  float* ybase = g_yr + r * (NROWS * 512) + (b * TT) * 512 + h * DV + v;

  float4 qf, kf, vf;
  float bf = 0.f, tf = 0.f;
  {
    const float* row = gpb + ls * NPROJ + h * 64;
    qf = *(const float4*)(row + lp * 4);
    kf = *(const float4*)(row + 512 + lp * 4);
    vf = *(const float4*)(row + 1024 + lp * 4);
    if (lp == 0) bf = gpb[ls * NPROJ + 1536 + h * RRm + r];
    if (lp == 1) tf = gpb[ls * NPROJ + 1600 + h * RRm + r];
  }
  *(float4*)(&sQ[0][ls][lp * 4]) = qf;
  *(float4*)(&sK[0][ls][lp * 4]) = kf;
  *(float4*)(&sV[0][ls][lp * 4]) = vf;
  if (lp == 0) sB[0][ls] = bf;
  if (lp == 1) sT[0][ls] = tf;
  __syncthreads();

  const int NCH = TT / CH;
  int cur = 0;
  for (int c = 0; c < NCH; c++) {
    // Prefetch next chunk into registers (overlaps with the 16-step compute)
    if (c + 1 < NCH) {
      const float* row = gpb + ((c + 1) * CH + ls) * NPROJ + h * 64;
      qf = *(const float4*)(row + lp * 4);
      kf = *(const float4*)(row + 512 + lp * 4);
      vf = *(const float4*)(row + 1024 + lp * 4);
      if (lp == 0) bf = gpb[((c + 1) * CH + ls) * NPROJ + 1536 + h * RRm + r];
      if (lp == 1) tf = gpb[((c + 1) * CH + ls) * NPROJ + 1600 + h * RRm + r];
    }

    for (int tt = 0; tt < CH; tt++) {
      u64 kt2[8], qt2[8];
#pragma unroll
      for (int g4 = 0; g4 < 4; g4++) {
        F4U kv; kv.f = *(const float4*)(&sK[cur][tt][k0 + g4 * 4]);
        F4U qv; qv.f = *(const float4*)(&sQ[cur][tt][k0 + g4 * 4]);
        kt2[g4 * 2 + 0] = kv.u[0]; kt2[g4 * 2 + 1] = kv.u[1];
        qt2[g4 * 2 + 0] = qv.u[0]; qt2[g4 * 2 + 1] = qv.u[1];
      }
      const float vtv  = sV[cur][tt][v];
      const float beta = sB[cur][tt];
      const float tg   = sT[cur][tt];
      const float decay = tg * rho;
      const u64 decay2 = pack2(decay, decay);
      const u64 wp2 = pack2(w_prev, w_prev);

      u64 AkA = 0ULL, AkB = 0ULL, BkA = 0ULL, BkB = 0ULL;
      u64 Rq2 = 0ULL, Kq2 = 0ULL;
#pragma unroll
      for (int p = 0; p < 8; p++) {
        u64 dc = mul2(decay2, cw2[p]);
        u64 ds = mul2(decay2, sw2[p]);
        u64 m  = mul2(ds, i2[p]);
        u64 a  = fma2(dc, r2[p], neg2(m));      // a = dc*r - ds*i  (w-independent)
        u64 m2 = mul2(dc, i2[p]);
        u64 cc = fma2(ds, r2[p], m2);           // c = ds*r + dc*i
        u64 bb = mul2(dc, kp2[p]);              // b = dc*k_prev
        u64 dd = mul2(ds, kp2[p]);              // d = ds*k_prev
        if (p & 1) { AkB = fma2(a, kt2[p], AkB); BkB = fma2(bb, kt2[p], BkB); }
        else       { AkA = fma2(a, kt2[p], AkA); BkA = fma2(bb, kt2[p], BkA); }
        r2[p] = fma2(wp2, bb, a);               // r_t = a + w_prev*b
        i2[p] = fma2(wp2, dd, cc);              // i_t = c + w_prev*d
        kp2[p] = kt2[p];
        Rq2 = fma2(r2[p], qt2[p], Rq2);
        Kq2 = fma2(kt2[p], qt2[p], Kq2);
      }
      float x0, x1, x2, x3;
      unpack2(AkA, x0, x1); unpack2(AkB, x2, x3);
      float Ak = (x0 + x2) + (x1 + x3);
      unpack2(BkA, x0, x1); unpack2(BkB, x2, x3);
      float Bk = (x0 + x2) + (x1 + x3);
      unpack2(Rq2, x0, x1);
      float Rq = x0 + x1;
      unpack2(Kq2, x0, x1);
      float Kq = x0 + x1;
      // four independent shfl reductions; Ak/Bk (and their shfls) do NOT
      // depend on w_prev -> off the loop-carried chain
      Ak += __shfl_xor_sync(0xffffffffu, Ak, 1);
      Bk += __shfl_xor_sync(0xffffffffu, Bk, 1);
      Rq += __shfl_xor_sync(0xffffffffu, Rq, 1);
      Kq += __shfl_xor_sync(0xffffffffu, Kq, 1);
      Ak += __shfl_xor_sync(0xffffffffu, Ak, 2);
      Bk += __shfl_xor_sync(0xffffffffu, Bk, 2);
      Rq += __shfl_xor_sync(0xffffffffu, Rq, 2);
      Kq += __shfl_xor_sync(0xffffffffu, Kq, 2);

      const float pred = fmaf(w_prev, Bk, Ak);
      const float w = beta * (vtv - pred);
      if (q4 == 0) ybase[(c * CH + tt) * 512] = mw * fmaf(w, Kq, Rq);
      w_prev = w;
    }

    if (c + 1 < NCH) {
      int nxt = cur ^ 1;
      *(float4*)(&sQ[nxt][ls][lp * 4]) = qf;
      *(float4*)(&sK[nxt][ls][lp * 4]) = kf;
      *(float4*)(&sV[nxt][ls][lp * 4]) = vf;
      if (lp == 0) sB[nxt][ls] = bf;
      if (lp == 1) sT[nxt][ls] = tf;
      __syncthreads();
      cur = nxt;
    }
  }
}

// ---------------------------------------------------------------------------
// Reduce over r + apply gate: g_a[row][c] = gate[row][c] * sum_r g_yr
// (gate already sigmoided in g_projc)
// ---------------------------------------------------------------------------
__global__ __launch_bounds__(256) void reduce_y_kernel() {
  int idx = blockIdx.x * blockDim.x + threadIdx.x;   // float4 index
  if (idx >= NROWS * 512 / 4) return;
  int row = idx >> 7;           // 128 float4 per row
  int c4 = (idx & 127) << 2;
  float4 s = *(const float4*)(g_yr + row * 512 + c4);
#pragma unroll
  for (int r = 1; r < RRm; r++) {
    float4 t = *(const float4*)(g_yr + r * (NROWS * 512) + row * 512 + c4);
    s.x += t.x; s.y += t.y; s.z += t.z; s.w += t.w;
  }
  float4 g = *(const float4*)(g_projc + row * NPROJ + 1664 + c4);
  s.x *= g.x; s.y *= g.y; s.z *= g.z; s.w *= g.w;
  *(float4*)(g_a + row * 512 + c4) = s;
}

// ---------------------------------------------------------------------------
// Output GEMM, split-K=4: g_o[z] = g_a[:, z*128:+128] @ Wo-slice
// grid (16, 4, 4) = 256 CTAs, 256 threads, 4x4 microtile, double-buffered.
// ---------------------------------------------------------------------------
__global__ __launch_bounds__(256) void out_gemm_kernel(
    const float* __restrict__ Wo) {
  __shared__ float As[2][16][68];
  __shared__ float Bs[2][16][64];

  const int colBase = blockIdx.x * 64;  // 0..1023
  const int rowBase = blockIdx.y * 64;  // 0..255
  const int kOff = blockIdx.z * 128;

  const int tid = threadIdx.x;
  const int ty = tid >> 4, tx = tid & 15;
  const int lrA = tid >> 2, kgA = (tid & 3) * 4;
  const int lkB = tid >> 4, c4B = (tid & 15) << 2;

  u64 acc[4][2];
#pragma unroll
  for (int i = 0; i < 4; i++) { acc[i][0] = 0ULL; acc[i][1] = 0ULL; }

  const int NIT = 128 / 16;
  float4 av, bv;
  av = *(const float4*)(g_a + (rowBase + lrA) * 512 + kOff + kgA);
  bv = *(const float4*)(Wo + (kOff + lkB) * DD + colBase + c4B);
  As[0][kgA + 0][lrA] = av.x; As[0][kgA + 1][lrA] = av.y;
  As[0][kgA + 2][lrA] = av.z; As[0][kgA + 3][lrA] = av.w;
  *(float4*)(&Bs[0][lkB][c4B]) = bv;
  __syncthreads();

  int cur = 0;
  for (int i = 0; i < NIT; i++) {
    if (i + 1 < NIT) {
      int kb = kOff + (i + 1) * 16;
      av = *(const float4*)(g_a + (rowBase + lrA) * 512 + kb + kgA);
      bv = *(const float4*)(Wo + (kb + lkB) * DD + colBase + c4B);
    }
#pragma unroll
    for (int kk = 0; kk < 16; kk++) {
      float4 a = *(float4*)(&As[cur][kk][ty * 4]);
      F4U bb; bb.f = *(float4*)(&Bs[cur][kk][tx * 4]);
      u64 a0 = pack2(a.x, a.x);
      u64 a1 = pack2(a.y, a.y);
      u64 a2 = pack2(a.z, a.z);
      u64 a3 = pack2(a.w, a.w);
      acc[0][0] = fma2(a0, bb.u[0], acc[0][0]);
      acc[0][1] = fma2(a0, bb.u[1], acc[0][1]);
      acc[1][0] = fma2(a1, bb.u[0], acc[1][0]);
      acc[1][1] = fma2(a1, bb.u[1], acc[1][1]);
      acc[2][0] = fma2(a2, bb.u[0], acc[2][0]);
      acc[2][1] = fma2(a2, bb.u[1], acc[2][1]);
      acc[3][0] = fma2(a3, bb.u[0], acc[3][0]);
      acc[3][1] = fma2(a3, bb.u[1], acc[3][1]);
    }
    if (i + 1 < NIT) {
      int nxt = cur ^ 1;
      As[nxt][kgA + 0][lrA] = av.x; As[nxt][kgA + 1][lrA] = av.y;
      As[nxt][kgA + 2][lrA] = av.z; As[nxt][kgA + 3][lrA] = av.w;
      *(float4*)(&Bs[nxt][lkB][c4B]) = bv;
      __syncthreads();
      cur = nxt;
    }
  }

  float* outp = g_o + blockIdx.z * (NROWS * DD);
#pragma unroll
  for (int j = 0; j < 4; j++) {
    F4U o; o.u[0] = acc[j][0]; o.u[1] = acc[j][1];
    *(float4*)(outp + (rowBase + ty * 4 + j) * DD + colBase + tx * 4) = o.f;
  }
}

// ---------------------------------------------------------------------------
// Sum the four out partials into d_out.
// ---------------------------------------------------------------------------
__global__ __launch_bounds__(256) void out_sum_kernel(float* __restrict__ out) {
  int idx = blockIdx.x * blockDim.x + threadIdx.x;   // float4 index
  if (idx >= NROWS * DD / 4) return;
  float4 a = *(const float4*)(g_o + idx * 4);
  float4 b = *(const float4*)(g_o + NROWS * DD + idx * 4);
  float4 c = *(const float4*)(g_o + 2 * NROWS * DD + idx * 4);
  float4 d = *(const float4*)(g_o + 3 * NROWS * DD + idx * 4);
  float4 s;
  s.x = (a.x + b.x) + (c.x + d.x);
  s.y = (a.y + b.y) + (c.y + d.y);
  s.z = (a.z + b.z) + (c.z + d.z);
  s.w = (a.w + b.w) + (c.w + d.w);
  *(float4*)(out + idx * 4) = s;
}

// ---------------------------------------------------------------------------
// Entry point
// ---------------------------------------------------------------------------
extern "C" void kernel_launch(void* const* d_in, const int* in_sizes, int n_in,
                              void* d_out, int out_size) {
  const float* x    = (const float*)d_in[0];
  const float* Wq   = (const float*)d_in[1];
  const float* Wk   = (const float*)d_in[2];
  const float* Wv   = (const float*)d_in[3];
  const float* Wb   = (const float*)d_in[4];
  const float* Wtg  = (const float*)d_in[5];
  const float* ml   = (const float*)d_in[6];
  const float* ldc  = (const float*)d_in[7];
  const float* oms  = (const float*)d_in[8];
  const float* Wg   = (const float*)d_in[9];
  const float* Wo   = (const float*)d_in[10];
  float* out = (float*)d_out;

  proj_gemm_kernel<<<dim3(NPROJ / 64, NROWS / 64, 2), 256>>>(x, Wq, Wk, Wv, Wb, Wtg, Wg);
  proj_combine_kernel<<<(NROWS * NPROJ / 4 + 255) / 256, 256>>>();
  scan_kernel<<<BB * HH * RRm, 256>>>(ml, ldc, oms);
  reduce_y_kernel<<<(NROWS * 512 / 4 + 255) / 256, 256>>>();
  out_gemm_kernel<<<dim3(DD / 64, NROWS / 64, 4), 256>>>(Wo);
  out_sum_kernel<<<(NROWS * DD / 4 + 255) / 256, 256>>>(out);
}

// round 14
// speedup vs baseline: 1.1737x; 1.0749x over previous
#include <cuda_runtime.h>
#include <math.h>

// Problem constants
#define BB 2
#define TT 128
#define DD 1024
#define HH 8
#define RRm 8
#define DK 64
#define DV 64
#define NPROJ 2176           // 512 q | 512 k | 512 v | 64 beta | 64 tg | 512 g
#define NROWS 256            // B*T
#define CH 16                // scan chunk (timesteps staged in smem)

typedef unsigned long long u64;

// Scratch (no allocations allowed)
__device__ __align__(16) float g_proj[2 * NROWS * NPROJ];      // split-K partials (raw)
__device__ __align__(16) float g_projc[NROWS * NPROJ];         // combined + activated
__device__ __align__(16) float g_yr[RRm * NROWS * 512];        // per-r mode reads
__device__ __align__(16) float g_a[NROWS * 512];               // gated, r-reduced
__device__ __align__(16) float g_o[2 * NROWS * DD];            // out partials (split-K=2)

// ---------------------------------------------------------------------------
// f32x2 helpers (ptxas never emits FFMA2 from C++; PTX only)
// ---------------------------------------------------------------------------
__device__ __forceinline__ u64 pack2(float lo, float hi) {
  u64 r; asm("mov.b64 %0, {%1, %2};" : "=l"(r) : "f"(lo), "f"(hi)); return r;
}
__device__ __forceinline__ void unpack2(u64 v, float& lo, float& hi) {
  asm("mov.b64 {%0, %1}, %2;" : "=f"(lo), "=f"(hi) : "l"(v));
}
__device__ __forceinline__ u64 fma2(u64 a, u64 b, u64 c) {
  u64 d; asm("fma.rn.f32x2 %0, %1, %2, %3;" : "=l"(d) : "l"(a), "l"(b), "l"(c)); return d;
}
__device__ __forceinline__ u64 mul2(u64 a, u64 b) {
  u64 d; asm("mul.rn.f32x2 %0, %1, %2;" : "=l"(d) : "l"(a), "l"(b)); return d;
}
__device__ __forceinline__ u64 neg2(u64 a) { return a ^ 0x8000000080000000ULL; }

union F4U { float4 f; u64 u[2]; };

__device__ __forceinline__ float sigmoidf_(float x) { return 1.f / (1.f + expf(-x)); }

// ---------------------------------------------------------------------------
// Fused projection GEMM, split-K=2: g_proj[z] = x[:, z*512:+512] @ W-half
// grid (34, 4, 2) = 272 CTAs, 256 threads, 4x4 microtile, double-buffered.
// ---------------------------------------------------------------------------
__global__ __launch_bounds__(256) void proj_gemm_kernel(
    const float* __restrict__ x,
    const float* __restrict__ Wq, const float* __restrict__ Wk,
    const float* __restrict__ Wv, const float* __restrict__ Wb,
    const float* __restrict__ Wtg, const float* __restrict__ Wg) {
  __shared__ float As[2][16][68];
  __shared__ float Bs[2][16][64];

  const int colBase = blockIdx.x * 64;
  const int rowBase = blockIdx.y * 64;
  const int kOff = blockIdx.z * 512;

  const float* W; int lc, ldw;
  if (colBase < 512)       { W = Wq;  lc = colBase;        ldw = 512; }
  else if (colBase < 1024) { W = Wk;  lc = colBase - 512;  ldw = 512; }
  else if (colBase < 1536) { W = Wv;  lc = colBase - 1024; ldw = 512; }
  else if (colBase < 1600) { W = Wb;  lc = colBase - 1536; ldw = 64;  }
  else if (colBase < 1664) { W = Wtg; lc = colBase - 1600; ldw = 64;  }
  else                     { W = Wg;  lc = colBase - 1664; ldw = 512; }

  const int tid = threadIdx.x;
  const int ty = tid >> 4, tx = tid & 15;
  const int lrA = tid >> 2, kgA = (tid & 3) * 4;
  const int lkB = tid >> 4, c4B = (tid & 15) << 2;

  u64 acc[4][2];
#pragma unroll
  for (int i = 0; i < 4; i++) { acc[i][0] = 0ULL; acc[i][1] = 0ULL; }

  const int NIT = 512 / 16;
  float4 av, bv;
  av = *(const float4*)(x + (rowBase + lrA) * DD + kOff + kgA);
  bv = *(const float4*)(W + (kOff + lkB) * ldw + lc + c4B);
  As[0][kgA + 0][lrA] = av.x; As[0][kgA + 1][lrA] = av.y;
  As[0][kgA + 2][lrA] = av.z; As[0][kgA + 3][lrA] = av.w;
  *(float4*)(&Bs[0][lkB][c4B]) = bv;
  __syncthreads();

  int cur = 0;
  for (int i = 0; i < NIT; i++) {
    if (i + 1 < NIT) {
      int kb = kOff + (i + 1) * 16;
      av = *(const float4*)(x + (rowBase + lrA) * DD + kb + kgA);
      bv = *(const float4*)(W + (kb + lkB) * ldw + lc + c4B);
    }
#pragma unroll
    for (int kk = 0; kk < 16; kk++) {
      float4 a = *(float4*)(&As[cur][kk][ty * 4]);
      F4U bb; bb.f = *(float4*)(&Bs[cur][kk][tx * 4]);
      u64 a0 = pack2(a.x, a.x);
      u64 a1 = pack2(a.y, a.y);
      u64 a2 = pack2(a.z, a.z);
      u64 a3 = pack2(a.w, a.w);
      acc[0][0] = fma2(a0, bb.u[0], acc[0][0]);
      acc[0][1] = fma2(a0, bb.u[1], acc[0][1]);
      acc[1][0] = fma2(a1, bb.u[0], acc[1][0]);
      acc[1][1] = fma2(a1, bb.u[1], acc[1][1]);
      acc[2][0] = fma2(a2, bb.u[0], acc[2][0]);
      acc[2][1] = fma2(a2, bb.u[1], acc[2][1]);
      acc[3][0] = fma2(a3, bb.u[0], acc[3][0]);
      acc[3][1] = fma2(a3, bb.u[1], acc[3][1]);
    }
    if (i + 1 < NIT) {
      int nxt = cur ^ 1;
      As[nxt][kgA + 0][lrA] = av.x; As[nxt][kgA + 1][lrA] = av.y;
      As[nxt][kgA + 2][lrA] = av.z; As[nxt][kgA + 3][lrA] = av.w;
      *(float4*)(&Bs[nxt][lkB][c4B]) = bv;
      __syncthreads();
      cur = nxt;
    }
  }

  float* outp = g_proj + blockIdx.z * (NROWS * NPROJ);
#pragma unroll
  for (int j = 0; j < 4; j++) {
    F4U o; o.u[0] = acc[j][0]; o.u[1] = acc[j][1];
    *(float4*)(outp + (rowBase + ty * 4 + j) * NPROJ + colBase + tx * 4) = o.f;
  }
}

// ---------------------------------------------------------------------------
// Combine split-K proj halves + apply sigmoid to activation cols (>=1536).
// 128-thread blocks, 1088 blocks (latency-bound streamer: maximize CTAs).
// ---------------------------------------------------------------------------
__global__ __launch_bounds__(128) void proj_combine_kernel() {
  int idx = blockIdx.x * blockDim.x + threadIdx.x;   // float4 index
  if (idx >= NROWS * NPROJ / 4) return;
  int e = idx * 4;
  int col = e % NPROJ;
  float4 a = *(const float4*)(g_proj + e);
  float4 b = *(const float4*)(g_proj + NROWS * NPROJ + e);
  float4 s; s.x = a.x + b.x; s.y = a.y + b.y; s.z = a.z + b.z; s.w = a.w + b.w;
  if (col >= 1536) {
    s.x = sigmoidf_(s.x); s.y = sigmoidf_(s.y);
    s.z = sigmoidf_(s.z); s.w = sigmoidf_(s.w);
  }
  *(float4*)(g_projc + e) = s;
}

// ---------------------------------------------------------------------------
// Sequential scan (R10 champion version). One CTA per (b,h,r) chain:
// 128 CTAs, 256 threads. CH=16 steps staged in smem from the combined
// buffer. rd = rotq + w*kq trick: rotq/kq accumulate in the rotation loop
// so only one dependent shfl round sits on the serial chain.
// ---------------------------------------------------------------------------
__global__ __launch_bounds__(256) void scan_kernel(
    const float* __restrict__ mode_logits,
    const float* __restrict__ log_decay,
    const float* __restrict__ omega_log_scale) {
  __shared__ float sQ[2][CH][64];
  __shared__ float sK[2][CH][64];
  __shared__ float sV[2][CH][64];
  __shared__ float sB[2][CH];
  __shared__ float sT[2][CH];

  const int cid = blockIdx.x;        // 0..127
  const int b = cid >> 6;
  const int h = (cid >> 3) & 7;
  const int r = cid & 7;
  const int tid = threadIdx.x;
  const int v = tid >> 2;
  const int q4 = tid & 3;
  const int k0 = q4 * 16;

  // mode weight: softmax over R for this head
  float ml[RRm];
  float mx = -1e30f;
#pragma unroll
  for (int i = 0; i < RRm; i++) { ml[i] = mode_logits[h * RRm + i]; mx = fmaxf(mx, ml[i]); }
  float ssum = 0.f;
#pragma unroll
  for (int i = 0; i < RRm; i++) ssum += expf(ml[i] - mx);
  const float mw = expf(ml[r] - mx) / ssum;

  // rho = exp(-softplus(log_decay))
  const float ldv = log_decay[h * RRm + r];
  const float sp = (ldv > 20.f) ? ldv : log1pf(expf(ldv));
  const float rho = expf(-sp);
  const float osc = expf(omega_log_scale[h * RRm + r]);

  u64 cw2[8], sw2[8], sr2[8], si2[8];
  const float c_ln = 9.210340371976184f / 64.f;  // ln(10000)/64
#pragma unroll
  for (int p = 0; p < 8; p++) {
    float pv = (float)(k0 + 2 * p);              // even -> (k & ~1) identical for pair
    float om = osc * expf(-pv * c_ln);
    float c = cosf(om), s = sinf(om);
    cw2[p] = pack2(c, c);
    sw2[p] = pack2(s, s);
    sr2[p] = 0ULL;
    si2[p] = 0ULL;
  }

  // Cooperative chunk loading: thread -> (step ls, float4 part lp)
  const int ls = tid >> 4;       // 0..15
  const int lp = tid & 15;       // 0..15
  const float* gpb = g_projc + (b * TT) * NPROJ;
  float* ybase = g_yr + r * (NROWS * 512) + (b * TT) * 512 + h * DV + v;

  float4 qf, kf, vf;
  float bf = 0.f, tf = 0.f;
  {
    const float* row = gpb + ls * NPROJ + h * 64;
    qf = *(const float4*)(row + lp * 4);
    kf = *(const float4*)(row + 512 + lp * 4);
    vf = *(const float4*)(row + 1024 + lp * 4);
    if (lp == 0) bf = gpb[ls * NPROJ + 1536 + h * RRm + r];
    if (lp == 1) tf = gpb[ls * NPROJ + 1600 + h * RRm + r];
  }
  *(float4*)(&sQ[0][ls][lp * 4]) = qf;
  *(float4*)(&sK[0][ls][lp * 4]) = kf;
  *(float4*)(&sV[0][ls][lp * 4]) = vf;
  if (lp == 0) sB[0][ls] = bf;
  if (lp == 1) sT[0][ls] = tf;
  __syncthreads();

  const int NCH = TT / CH;
  int cur = 0;
  for (int c = 0; c < NCH; c++) {
    // Prefetch next chunk into registers (overlaps with the 16-step compute)
    if (c + 1 < NCH) {
      const float* row = gpb + ((c + 1) * CH + ls) * NPROJ + h * 64;
      qf = *(const float4*)(row + lp * 4);
      kf = *(const float4*)(row + 512 + lp * 4);
      vf = *(const float4*)(row + 1024 + lp * 4);
      if (lp == 0) bf = gpb[((c + 1) * CH + ls) * NPROJ + 1536 + h * RRm + r];
      if (lp == 1) tf = gpb[((c + 1) * CH + ls) * NPROJ + 1600 + h * RRm + r];
    }

    for (int tt = 0; tt < CH; tt++) {
      u64 kt2[8], qt2[8];
#pragma unroll
      for (int g4 = 0; g4 < 4; g4++) {
        F4U kv; kv.f = *(const float4*)(&sK[cur][tt][k0 + g4 * 4]);
        F4U qv; qv.f = *(const float4*)(&sQ[cur][tt][k0 + g4 * 4]);
        kt2[g4 * 2 + 0] = kv.u[0]; kt2[g4 * 2 + 1] = kv.u[1];
        qt2[g4 * 2 + 0] = qv.u[0]; qt2[g4 * 2 + 1] = qv.u[1];
      }
      const float vtv  = sV[cur][tt][v];
      const float beta = sB[cur][tt];
      const float tg   = sT[cur][tt];
      const float decay = tg * rho;
      const u64 decay2 = pack2(decay, decay);

      // rotation + three accumulators (pred critical; rotq/kq off-path)
      u64 predA = 0ULL, predB = 0ULL, rotq2 = 0ULL, kq2 = 0ULL;
#pragma unroll
      for (int p = 0; p < 8; p++) {
        u64 dc = mul2(decay2, cw2[p]);
        u64 ds = mul2(decay2, sw2[p]);
        u64 m1 = mul2(ds, si2[p]);
        u64 rr = fma2(dc, sr2[p], neg2(m1));
        u64 m2 = mul2(dc, si2[p]);
        si2[p] = fma2(ds, sr2[p], m2);
        sr2[p] = rr;                       // sr temporarily holds rot_r
        if (p & 1) predB = fma2(rr, kt2[p], predB);
        else       predA = fma2(rr, kt2[p], predA);
        rotq2 = fma2(rr, qt2[p], rotq2);
        kq2   = fma2(kt2[p], qt2[p], kq2);
      }
      float alo, ahi, blo, bhi;
      unpack2(predA, alo, ahi); unpack2(predB, blo, bhi);
      float pred = (alo + blo) + (ahi + bhi);
      float rqlo, rqhi, kqlo, kqhi;
      unpack2(rotq2, rqlo, rqhi); unpack2(kq2, kqlo, kqhi);
      float rotq = rqlo + rqhi;
      float kq = kqlo + kqhi;
      // three independent shfl reductions; latencies overlap
      pred += __shfl_xor_sync(0xffffffffu, pred, 1);
      rotq += __shfl_xor_sync(0xffffffffu, rotq, 1);
      kq   += __shfl_xor_sync(0xffffffffu, kq, 1);
      pred += __shfl_xor_sync(0xffffffffu, pred, 2);
      rotq += __shfl_xor_sync(0xffffffffu, rotq, 2);
      kq   += __shfl_xor_sync(0xffffffffu, kq, 2);

      const float w = beta * (vtv - pred);
      const u64 w2 = pack2(w, w);

      // state update (inter-step path); rd needs no second reduction
#pragma unroll
      for (int p = 0; p < 8; p++)
        sr2[p] = fma2(w2, kt2[p], sr2[p]); // sr_new = rot_r + beta*err*k

      if (q4 == 0) ybase[(c * CH + tt) * 512] = mw * fmaf(w, kq, rotq);
    }

    if (c + 1 < NCH) {
      int nxt = cur ^ 1;
      *(float4*)(&sQ[nxt][ls][lp * 4]) = qf;
      *(float4*)(&sK[nxt][ls][lp * 4]) = kf;
      *(float4*)(&sV[nxt][ls][lp * 4]) = vf;
      if (lp == 0) sB[nxt][ls] = bf;
      if (lp == 1) sT[nxt][ls] = tf;
      __syncthreads();
      cur = nxt;
    }
  }
}

// ---------------------------------------------------------------------------
// Reduce over r + apply gate: g_a[row][c] = gate[row][c] * sum_r g_yr
// 128-thread blocks, 256 blocks (latency-bound: maximize resident CTAs).
// ---------------------------------------------------------------------------
__global__ __launch_bounds__(128) void reduce_y_kernel() {
  int idx = blockIdx.x * blockDim.x + threadIdx.x;   // float4 index
  if (idx >= NROWS * 512 / 4) return;
  int row = idx >> 7;           // 128 float4 per row
  int c4 = (idx & 127) << 2;
  float4 s = *(const float4*)(g_yr + row * 512 + c4);
#pragma unroll
  for (int r = 1; r < RRm; r++) {
    float4 t = *(const float4*)(g_yr + r * (NROWS * 512) + row * 512 + c4);
    s.x += t.x; s.y += t.y; s.z += t.z; s.w += t.w;
  }
  float4 g = *(const float4*)(g_projc + row * NPROJ + 1664 + c4);
  s.x *= g.x; s.y *= g.y; s.z *= g.z; s.w *= g.w;
  *(float4*)(g_a + row * 512 + c4) = s;
}

// ---------------------------------------------------------------------------
// Output GEMM, split-K=2: g_o[z] = g_a[:, z*256:+256] @ Wo-half
// grid (16, 4, 2) = 128 CTAs, 256 threads, 4x4 microtile, double-buffered.
// ---------------------------------------------------------------------------
__global__ __launch_bounds__(256) void out_gemm_kernel(
    const float* __restrict__ Wo) {
  __shared__ float As[2][16][68];
  __shared__ float Bs[2][16][64];

  const int colBase = blockIdx.x * 64;  // 0..1023
  const int rowBase = blockIdx.y * 64;  // 0..255
  const int kOff = blockIdx.z * 256;

  const int tid = threadIdx.x;
  const int ty = tid >> 4, tx = tid & 15;
  const int lrA = tid >> 2, kgA = (tid & 3) * 4;
  const int lkB = tid >> 4, c4B = (tid & 15) << 2;

  u64 acc[4][2];
#pragma unroll
  for (int i = 0; i < 4; i++) { acc[i][0] = 0ULL; acc[i][1] = 0ULL; }

  const int NIT = 256 / 16;
  float4 av, bv;
  av = *(const float4*)(g_a + (rowBase + lrA) * 512 + kOff + kgA);
  bv = *(const float4*)(Wo + (kOff + lkB) * DD + colBase + c4B);
  As[0][kgA + 0][lrA] = av.x; As[0][kgA + 1][lrA] = av.y;
  As[0][kgA + 2][lrA] = av.z; As[0][kgA + 3][lrA] = av.w;
  *(float4*)(&Bs[0][lkB][c4B]) = bv;
  __syncthreads();

  int cur = 0;
  for (int i = 0; i < NIT; i++) {
    if (i + 1 < NIT) {
      int kb = kOff + (i + 1) * 16;
      av = *(const float4*)(g_a + (rowBase + lrA) * 512 + kb + kgA);
      bv = *(const float4*)(Wo + (kb + lkB) * DD + colBase + c4B);
    }
#pragma unroll
    for (int kk = 0; kk < 16; kk++) {
      float4 a = *(float4*)(&As[cur][kk][ty * 4]);
      F4U bb; bb.f = *(float4*)(&Bs[cur][kk][tx * 4]);
      u64 a0 = pack2(a.x, a.x);
      u64 a1 = pack2(a.y, a.y);
      u64 a2 = pack2(a.z, a.z);
      u64 a3 = pack2(a.w, a.w);
      acc[0][0] = fma2(a0, bb.u[0], acc[0][0]);
      acc[0][1] = fma2(a0, bb.u[1], acc[0][1]);
      acc[1][0] = fma2(a1, bb.u[0], acc[1][0]);
      acc[1][1] = fma2(a1, bb.u[1], acc[1][1]);
      acc[2][0] = fma2(a2, bb.u[0], acc[2][0]);
      acc[2][1] = fma2(a2, bb.u[1], acc[2][1]);
      acc[3][0] = fma2(a3, bb.u[0], acc[3][0]);
      acc[3][1] = fma2(a3, bb.u[1], acc[3][1]);
    }
    if (i + 1 < NIT) {
      int nxt = cur ^ 1;
      As[nxt][kgA + 0][lrA] = av.x; As[nxt][kgA + 1][lrA] = av.y;
      As[nxt][kgA + 2][lrA] = av.z; As[nxt][kgA + 3][lrA] = av.w;
      *(float4*)(&Bs[nxt][lkB][c4B]) = bv;
      __syncthreads();
      cur = nxt;
    }
  }

  float* outp = g_o + blockIdx.z * (NROWS * DD);
#pragma unroll
  for (int j = 0; j < 4; j++) {
    F4U o; o.u[0] = acc[j][0]; o.u[1] = acc[j][1];
    *(float4*)(outp + (rowBase + ty * 4 + j) * DD + colBase + tx * 4) = o.f;
  }
}

// ---------------------------------------------------------------------------
// Sum the two out partials into d_out. 128-thread blocks, 512 blocks.
// ---------------------------------------------------------------------------
__global__ __launch_bounds__(128) void out_sum_kernel(float* __restrict__ out) {
  int idx = blockIdx.x * blockDim.x + threadIdx.x;   // float4 index
  if (idx >= NROWS * DD / 4) return;
  float4 a = *(const float4*)(g_o + idx * 4);
  float4 b = *(const float4*)(g_o + NROWS * DD + idx * 4);
  float4 s; s.x = a.x + b.x; s.y = a.y + b.y; s.z = a.z + b.z; s.w = a.w + b.w;
  *(float4*)(out + idx * 4) = s;
}

// ---------------------------------------------------------------------------
// Entry point
// ---------------------------------------------------------------------------
extern "C" void kernel_launch(void* const* d_in, const int* in_sizes, int n_in,
                              void* d_out, int out_size) {
  const float* x    = (const float*)d_in[0];
  const float* Wq   = (const float*)d_in[1];
  const float* Wk   = (const float*)d_in[2];
  const float* Wv   = (const float*)d_in[3];
  const float* Wb   = (const float*)d_in[4];
  const float* Wtg  = (const float*)d_in[5];
  const float* ml   = (const float*)d_in[6];
  const float* ldc  = (const float*)d_in[7];
  const float* oms  = (const float*)d_in[8];
  const float* Wg   = (const float*)d_in[9];
  const float* Wo   = (const float*)d_in[10];
  float* out = (float*)d_out;

  proj_gemm_kernel<<<dim3(NPROJ / 64, NROWS / 64, 2), 256>>>(x, Wq, Wk, Wv, Wb, Wtg, Wg);
  proj_combine_kernel<<<(NROWS * NPROJ / 4 + 127) / 128, 128>>>();
  scan_kernel<<<BB * HH * RRm, 256>>>(ml, ldc, oms);
  reduce_y_kernel<<<(NROWS * 512 / 4 + 127) / 128, 128>>>();
  out_gemm_kernel<<<dim3(DD / 64, NROWS / 64, 2), 256>>>(Wo);
  out_sum_kernel<<<(NROWS * DD / 4 + 127) / 128, 128>>>(out);
}